// round 8
// baseline (speedup 1.0000x reference)
#include <cuda_runtime.h>
#include <cstdint>

#define M_OUT 2049
#define MPAD  2176          // 17 * 128
#define NSIG  4096
#define KDIM  4096

static constexpr float CANG = (float)(-2.0 * 3.14 / 4096.0);
static constexpr float DEN  = (float)(4096.0 / 30.0);

__device__ float g_mean[KDIM];
__device__ float2 g_w2[(size_t)MPAD * KDIM];             // (cos, sin) table, rows >= 2049 zero
__device__ unsigned long long g_best[M_OUT];

// ---------- packed f32x2 helpers ----------
__device__ __forceinline__ unsigned long long pack2(float lo, float hi) {
    unsigned long long r;
    asm("mov.b64 %0, {%1, %2};" : "=l"(r) : "f"(lo), "f"(hi));
    return r;
}
__device__ __forceinline__ void unpack2(unsigned long long v, float& lo, float& hi) {
    asm("mov.b64 {%0, %1}, %2;" : "=f"(lo), "=f"(hi) : "l"(v));
}
__device__ __forceinline__ unsigned long long ffma2(unsigned long long a,
                                                    unsigned long long b,
                                                    unsigned long long c) {
    asm("fma.rn.f32x2 %0, %1, %2, %0;" : "+l"(c) : "l"(a), "l"(b));
    return c;
}

// ---------- kernel 1: per-row means ----------
__global__ void mean_kernel(const float* __restrict__ x) {
    __shared__ float red[256];
    const int n = blockIdx.x;
    const float4* row = (const float4*)(x + (size_t)n * NSIG);
    float s = 0.f;
#pragma unroll
    for (int c = 0; c < 4; ++c) {
        float4 v = row[threadIdx.x + c * 256];
        s += (v.x + v.y) + (v.z + v.w);
    }
    red[threadIdx.x] = s;
    __syncthreads();
    for (int off = 128; off > 0; off >>= 1) {
        if (threadIdx.x < off) red[threadIdx.x] += red[threadIdx.x + off];
        __syncthreads();
    }
    if (threadIdx.x == 0) g_mean[n] = red[0] * (1.0f / 4096.0f);
}

// ---------- kernel 2: trig table + reset argmax state (pure fp32) ----------
__global__ void trig_kernel() {
    const long long idx = (long long)blockIdx.x * blockDim.x + threadIdx.x;
    if (idx >= (long long)MPAD * KDIM) return;
    const int i = (int)(idx >> 12);
    const int n = (int)(idx & 4095);
    float2 w;
    if (i < M_OUT) {
        const float t = (float)(i * n);          // exact (< 2^23)
        const float a = CANG * t;                // one rounding, same as reference
        const float kf = rintf(a * 0.63661977236758134f); // a * 2/pi, |kf| <= 8187
        const int   k  = (int)kf;
        float r = fmaf(kf, -1.57079601287841796875f,   a);
        r       = fmaf(kf, -3.1391647326017916e-07f,   r);
        r       = fmaf(kf, -5.3903025299577648e-15f,   r);
        const float z = r * r;
        const float sinp = r * fmaf(z, fmaf(z, fmaf(z, -1.9515295891e-4f,
                                                8.3321608736e-3f),
                                        -1.6666654611e-1f), 1.0f);
        const float cosp = fmaf(z, fmaf(z, fmaf(z, fmaf(z, 2.443315711809948e-5f,
                                                    -1.388731625493765e-3f),
                                            4.166664568298827e-2f),
                                    -0.5f), 1.0f);
        const int q = k & 3;
        float c, s;
        if (q == 0)      { c =  cosp; s =  sinp; }
        else if (q == 1) { c = -sinp; s =  cosp; }
        else if (q == 2) { c = -cosp; s = -sinp; }
        else             { c =  sinp; s = -cosp; }
        w = make_float2(c, s);
    } else {
        w = make_float2(0.f, 0.f);
    }
    g_w2[idx] = w;
    if (idx < M_OUT) g_best[idx] = 0ull;
}

// ---------- kernel 3: dual GEMM (FFMA2) + fused argmax, 128x64 tile, 8x4/thread ----------
__global__ __launch_bounds__(256, 2) void gemm_argmax_kernel(const float* __restrict__ x) {
    __shared__ float2 As[16][130];                // (cos,sin) pairs, [k][i], stride 1040B
    __shared__ float  Bs[16][68];                 // [k][j], stride 272B
    __shared__ unsigned long long sbest[128];

    const int tid = threadIdx.x;
    const int i0 = blockIdx.y * 128;
    const int j0 = blockIdx.x * 64;

    // A loader: row = tid&127, half = tid>>7 covers k-chunks {0,8}
    const int arow = tid & 127;
    const int akb  = (tid >> 7) << 3;            // 0 or 8
    // B loader
    const int bk = tid >> 4;                     // 0..15
    const int bj = (tid & 15) << 2;              // 0..60
    // compute mapping: 8 i rows x 4 j cols per thread
    const int ty8 = (tid >> 4) << 3;             // i offset 0..120
    const int tx4 = (tid & 15) << 2;             // j offset 0..60

    if (tid < 128) sbest[tid] = 0ull;

    const float2* __restrict__ wrow = g_w2 + (size_t)(i0 + arow) * KDIM;

    unsigned long long acc[8][4];
#pragma unroll
    for (int a = 0; a < 8; ++a)
#pragma unroll
        for (int b = 0; b < 4; ++b) acc[a][b] = 0ull;

    // prefetch tile 0
    float4 pa[4];
#pragma unroll
    for (int c = 0; c < 4; ++c)
        pa[c] = *(const float4*)(wrow + akb + 2 * c);
    float4 pb = *(const float4*)(x + (size_t)bk * NSIG + (j0 + bj));
    float  pm = g_mean[bk];

    for (int kt = 0; kt < KDIM / 16; ++kt) {
#pragma unroll
        for (int c = 0; c < 4; ++c) {
            As[akb + 2 * c + 0][arow] = make_float2(pa[c].x, pa[c].y);
            As[akb + 2 * c + 1][arow] = make_float2(pa[c].z, pa[c].w);
        }
        *(float4*)(&Bs[bk][bj]) = make_float4(pb.x - pm, pb.y - pm, pb.z - pm, pb.w - pm);
        __syncthreads();

        if (kt + 1 < KDIM / 16) {
            const int kbase = (kt + 1) * 16;
#pragma unroll
            for (int c = 0; c < 4; ++c)
                pa[c] = *(const float4*)(wrow + kbase + akb + 2 * c);
            pb = *(const float4*)(x + (size_t)(kbase + bk) * NSIG + (j0 + bj));
            pm = g_mean[kbase + bk];
        }

#pragma unroll
        for (int kk = 0; kk < 16; ++kk) {
            const ulonglong2* ap = (const ulonglong2*)(&As[kk][ty8]);
            const ulonglong2 a01 = ap[0];
            const ulonglong2 a23 = ap[1];
            const ulonglong2 a45 = ap[2];
            const ulonglong2 a67 = ap[3];
            const float4 b4 = *(const float4*)(&Bs[kk][tx4]);
            const unsigned long long b0 = pack2(b4.x, b4.x);
            const unsigned long long b1 = pack2(b4.y, b4.y);
            const unsigned long long b2 = pack2(b4.z, b4.z);
            const unsigned long long b3 = pack2(b4.w, b4.w);
            acc[0][0] = ffma2(a01.x, b0, acc[0][0]);
            acc[0][1] = ffma2(a01.x, b1, acc[0][1]);
            acc[0][2] = ffma2(a01.x, b2, acc[0][2]);
            acc[0][3] = ffma2(a01.x, b3, acc[0][3]);
            acc[1][0] = ffma2(a01.y, b0, acc[1][0]);
            acc[1][1] = ffma2(a01.y, b1, acc[1][1]);
            acc[1][2] = ffma2(a01.y, b2, acc[1][2]);
            acc[1][3] = ffma2(a01.y, b3, acc[1][3]);
            acc[2][0] = ffma2(a23.x, b0, acc[2][0]);
            acc[2][1] = ffma2(a23.x, b1, acc[2][1]);
            acc[2][2] = ffma2(a23.x, b2, acc[2][2]);
            acc[2][3] = ffma2(a23.x, b3, acc[2][3]);
            acc[3][0] = ffma2(a23.y, b0, acc[3][0]);
            acc[3][1] = ffma2(a23.y, b1, acc[3][1]);
            acc[3][2] = ffma2(a23.y, b2, acc[3][2]);
            acc[3][3] = ffma2(a23.y, b3, acc[3][3]);
            acc[4][0] = ffma2(a45.x, b0, acc[4][0]);
            acc[4][1] = ffma2(a45.x, b1, acc[4][1]);
            acc[4][2] = ffma2(a45.x, b2, acc[4][2]);
            acc[4][3] = ffma2(a45.x, b3, acc[4][3]);
            acc[5][0] = ffma2(a45.y, b0, acc[5][0]);
            acc[5][1] = ffma2(a45.y, b1, acc[5][1]);
            acc[5][2] = ffma2(a45.y, b2, acc[5][2]);
            acc[5][3] = ffma2(a45.y, b3, acc[5][3]);
            acc[6][0] = ffma2(a67.x, b0, acc[6][0]);
            acc[6][1] = ffma2(a67.x, b1, acc[6][1]);
            acc[6][2] = ffma2(a67.x, b2, acc[6][2]);
            acc[6][3] = ffma2(a67.x, b3, acc[6][3]);
            acc[7][0] = ffma2(a67.y, b0, acc[7][0]);
            acc[7][1] = ffma2(a67.y, b1, acc[7][1]);
            acc[7][2] = ffma2(a67.y, b2, acc[7][2]);
            acc[7][3] = ffma2(a67.y, b3, acc[7][3]);
        }
        __syncthreads();
    }

    // fused argmax epilogue: amp^2 = re^2 + im^2 (sqrt & /Ns are monotone)
#pragma unroll
    for (int ti = 0; ti < 8; ++ti) {
        float bestv = -1.0f;
        unsigned bestj = 0;
#pragma unroll
        for (int tj = 0; tj < 4; ++tj) {
            float re, im;
            unpack2(acc[ti][tj], re, im);
            const float v = fmaf(re, re, im * im);
            const unsigned j = (unsigned)(j0 + tx4 + tj);
            if (v > bestv) { bestv = v; bestj = j; }   // ascending j: ties keep smallest j
        }
        const unsigned long long p =
            ((unsigned long long)__float_as_uint(bestv) << 32) |
            (unsigned long long)(0xFFFFFFFFu - bestj);          // ties -> smaller j wins
        atomicMax(&sbest[ty8 + ti], p);
    }
    __syncthreads();
    if (tid < 128) {
        const int gi = i0 + tid;
        if (gi < M_OUT) atomicMax(&g_best[gi], sbest[tid]);
    }
}

// ---------- kernel 4: map argmax index -> heart rate ----------
__global__ void final_kernel(float* __restrict__ out) {
    const int i = blockIdx.x * blockDim.x + threadIdx.x;
    if (i < M_OUT) {
        const unsigned j = 0xFFFFFFFFu - (unsigned)(g_best[i] & 0xFFFFFFFFull);
        const float freq = (float)j / DEN;     // matches jnp.arange(Ns)/(Ns/FPS)
        out[i] = freq * 60.0f;
    }
}

extern "C" void kernel_launch(void* const* d_in, const int* in_sizes, int n_in,
                              void* d_out, int out_size) {
    const float* x = (const float*)d_in[0];
    float* out = (float*)d_out;

    mean_kernel<<<KDIM, 256>>>(x);

    const long long trig_total = (long long)MPAD * KDIM;
    trig_kernel<<<(unsigned)((trig_total + 255) / 256), 256>>>();

    dim3 grid(NSIG / 64, MPAD / 128);   // 64 x 17
    gemm_argmax_kernel<<<grid, 256>>>(x);

    final_kernel<<<(M_OUT + 255) / 256, 256>>>(out);
}